// round 1
// baseline (speedup 1.0000x reference)
#include <cuda_runtime.h>
#include <math.h>

#define EPSF 1e-8f
#define NMAX 50000
#define D1 128
#define D2 256

// Scratch (device globals — no allocation allowed). float4 for 16B alignment.
__device__ float4 g_agg1_[(size_t)NMAX * D1 / 4];
__device__ float4 g_h_[(size_t)NMAX * D2 / 4];
__device__ float4 g_agg2_[(size_t)NMAX * D2 / 4];
__device__ float  g_xnorm[NMAX];
__device__ float  g_hnorm[NMAX];
__device__ int    g_is64;

// ---------------------------------------------------------------------------
// edge_index dtype detection (jax may serialize int64 as int32)
// ---------------------------------------------------------------------------
__global__ void k_init_flag() { g_is64 = 1; }

__global__ void k_detect64(const void* __restrict__ eidx, int E, int N) {
    int i = blockIdx.x * blockDim.x + threadIdx.x;
    if (i < E) {
        long long v = ((const long long*)eidx)[i];
        if (v < 0 || v >= (long long)N) g_is64 = 0;
    }
}

// ---------------------------------------------------------------------------
// Per-node norms + self-loop init: agg[i] = (sim_self > 0.5) ? feat[i] : 0
// sim_self = dot/max(norm*norm, eps), dot = sum(feat^2)
// ---------------------------------------------------------------------------
template<int D>
__global__ void k_norms_init(const float* __restrict__ feat,
                             float* __restrict__ norms,
                             float* __restrict__ agg, int N)
{
    int node = (blockIdx.x * blockDim.x + threadIdx.x) >> 5;
    int lane = threadIdx.x & 31;
    if (node >= N) return;
    const float4* f = (const float4*)(feat + (size_t)node * D);
    float4* a = (float4*)(agg + (size_t)node * D);
    float4 v[D / 128];
    float n2 = 0.f;
#pragma unroll
    for (int i = 0; i < D / 128; i++) {
        v[i] = f[lane + 32 * i];
        n2 += v[i].x * v[i].x + v[i].y * v[i].y + v[i].z * v[i].z + v[i].w * v[i].w;
    }
#pragma unroll
    for (int o = 16; o; o >>= 1) n2 += __shfl_xor_sync(0xffffffffu, n2, o);
    float nrm = sqrtf(n2);
    if (lane == 0) norms[node] = nrm;
    float denom = fmaxf(nrm * nrm, EPSF);
    bool pass = n2 > 0.5f * denom;
    float4 z = make_float4(0.f, 0.f, 0.f, 0.f);
#pragma unroll
    for (int i = 0; i < D / 128; i++) a[lane + 32 * i] = pass ? v[i] : z;
}

// ---------------------------------------------------------------------------
// Edge pass: one warp per edge. dot(feat[s], feat[d]); if cos > 0.5,
// atomically add feat[s] into agg[d].
// ---------------------------------------------------------------------------
template<int D>
__global__ void k_edge_pass(const float* __restrict__ feat,
                            const float* __restrict__ norms,
                            const void* __restrict__ eidx,
                            float* __restrict__ agg, int E)
{
    int e = (int)((blockIdx.x * (unsigned)blockDim.x + threadIdx.x) >> 5);
    if (e >= E) return;
    int lane = threadIdx.x & 31;
    int s, d;
    if (g_is64) {
        const long long* p = (const long long*)eidx;
        s = (int)p[e];
        d = (int)p[e + E];
    } else {
        const int* p = (const int*)eidx;
        s = p[e];
        d = p[e + E];
    }
    const float4* fs = (const float4*)(feat + (size_t)s * D);
    const float4* fd = (const float4*)(feat + (size_t)d * D);
    float4 vs[D / 128];
    float dot = 0.f;
#pragma unroll
    for (int i = 0; i < D / 128; i++) {
        vs[i] = fs[lane + 32 * i];
        float4 vd = fd[lane + 32 * i];
        dot += vs[i].x * vd.x + vs[i].y * vd.y + vs[i].z * vd.z + vs[i].w * vd.w;
    }
#pragma unroll
    for (int o = 16; o; o >>= 1) dot += __shfl_xor_sync(0xffffffffu, dot, o);
    float thr = 0.5f * fmaxf(norms[s] * norms[d], EPSF);
    if (dot > thr) {
        float* out = agg + (size_t)d * D + lane * 4;
#pragma unroll
        for (int i = 0; i < D / 128; i++) {
            asm volatile("red.global.add.v4.f32 [%0], {%1,%2,%3,%4};" ::
                         "l"(out + i * 128),
                         "f"(vs[i].x), "f"(vs[i].y), "f"(vs[i].z), "f"(vs[i].w)
                         : "memory");
        }
    }
}

// ---------------------------------------------------------------------------
// SGEMM: C[M,N] = A[M,K] @ W[N,K]^T + bias, optional relu.
// Register-tiled, smem-staged.
// ---------------------------------------------------------------------------
template<int BM, int BN, int BK, int TM, int TN>
__global__ __launch_bounds__((BM / TM) * (BN / TN))
void k_sgemm(const float* __restrict__ A, const float* __restrict__ W,
             const float* __restrict__ bias, float* __restrict__ C,
             int M, int N, int K, int do_relu)
{
    constexpr int THREADS = (BM / TM) * (BN / TN);
    __shared__ float As[BK][BM];
    __shared__ float Ws[BK][BN];
    int tid = threadIdx.x;
    int tx = tid % (BN / TN);
    int ty = tid / (BN / TN);
    int m0 = blockIdx.y * BM;
    int n0 = blockIdx.x * BN;

    float acc[TM][TN] = {};
    constexpr int A_LD = BM * BK / 4;  // float4 loads for A tile
    constexpr int W_LD = BN * BK / 4;

    for (int k0 = 0; k0 < K; k0 += BK) {
#pragma unroll
        for (int i = tid; i < A_LD; i += THREADS) {
            int m = i / (BK / 4);
            int kq = i % (BK / 4);
            int gm = m0 + m;
            if (gm >= M) gm = M - 1;  // clamp; stores are guarded
            float4 v = *(const float4*)(A + (size_t)gm * K + k0 + kq * 4);
            As[kq * 4 + 0][m] = v.x;
            As[kq * 4 + 1][m] = v.y;
            As[kq * 4 + 2][m] = v.z;
            As[kq * 4 + 3][m] = v.w;
        }
#pragma unroll
        for (int i = tid; i < W_LD; i += THREADS) {
            int n = i / (BK / 4);
            int kq = i % (BK / 4);
            float4 v = *(const float4*)(W + (size_t)(n0 + n) * K + k0 + kq * 4);
            Ws[kq * 4 + 0][n] = v.x;
            Ws[kq * 4 + 1][n] = v.y;
            Ws[kq * 4 + 2][n] = v.z;
            Ws[kq * 4 + 3][n] = v.w;
        }
        __syncthreads();
#pragma unroll
        for (int k = 0; k < BK; k++) {
            float rm[TM], rn[TN];
#pragma unroll
            for (int i = 0; i < TM; i++) rm[i] = As[k][ty * TM + i];
#pragma unroll
            for (int j = 0; j < TN; j++) rn[j] = Ws[k][tx * TN + j];
#pragma unroll
            for (int i = 0; i < TM; i++)
#pragma unroll
                for (int j = 0; j < TN; j++)
                    acc[i][j] += rm[i] * rn[j];
        }
        __syncthreads();
    }
#pragma unroll
    for (int i = 0; i < TM; i++) {
        int gm = m0 + ty * TM + i;
        if (gm >= M) continue;
#pragma unroll
        for (int j = 0; j < TN; j++) {
            int gn = n0 + tx * TN + j;
            float v = acc[i][j] + bias[gn];
            if (do_relu) v = fmaxf(v, 0.f);
            C[(size_t)gm * N + gn] = v;
        }
    }
}

// ---------------------------------------------------------------------------
// log_softmax over rows of 64 (warp per row, 2 elems/lane)
// ---------------------------------------------------------------------------
__global__ void k_logsoftmax64(float* __restrict__ out, int N)
{
    int row = (blockIdx.x * blockDim.x + threadIdx.x) >> 5;
    int lane = threadIdx.x & 31;
    if (row >= N) return;
    float* p = out + (size_t)row * 64;
    float2 v = *(float2*)(p + lane * 2);
    float m = fmaxf(v.x, v.y);
#pragma unroll
    for (int o = 16; o; o >>= 1) m = fmaxf(m, __shfl_xor_sync(0xffffffffu, m, o));
    float s = expf(v.x - m) + expf(v.y - m);
#pragma unroll
    for (int o = 16; o; o >>= 1) s += __shfl_xor_sync(0xffffffffu, s, o);
    float l = m + logf(s);
    v.x -= l;
    v.y -= l;
    *(float2*)(p + lane * 2) = v;
}

// ---------------------------------------------------------------------------
extern "C" void kernel_launch(void* const* d_in, const int* in_sizes, int n_in,
                              void* d_out, int out_size)
{
    const float* x   = (const float*)d_in[0];
    const void*  eix = d_in[1];
    const float* W1  = (const float*)d_in[2];
    const float* b1  = (const float*)d_in[3];
    const float* W2  = (const float*)d_in[4];
    const float* b2  = (const float*)d_in[5];
    float* out = (float*)d_out;

    int N = in_sizes[0] / D1;      // 50000
    int E = in_sizes[1] / 2;       // 800000
    (void)n_in; (void)out_size;

    float *agg1, *h, *agg2, *xn, *hn;
    cudaGetSymbolAddress((void**)&agg1, g_agg1_);
    cudaGetSymbolAddress((void**)&h,    g_h_);
    cudaGetSymbolAddress((void**)&agg2, g_agg2_);
    cudaGetSymbolAddress((void**)&xn,   g_xnorm);
    cudaGetSymbolAddress((void**)&hn,   g_hnorm);

    // dtype detection for edge_index
    k_init_flag<<<1, 1>>>();
    k_detect64<<<(E + 255) / 256, 256>>>(eix, E, N);

    int nodeBlocks = (N * 32 + 255) / 256;
    int edgeBlocks = (int)(((long long)E * 32 + 255) / 256);

    // ---- Layer 1 ----
    k_norms_init<D1><<<nodeBlocks, 256>>>(x, xn, agg1, N);
    k_edge_pass<D1><<<edgeBlocks, 256>>>(x, xn, eix, agg1, E);
    {
        dim3 grid(256 / 128, (N + 127) / 128);
        k_sgemm<128, 128, 16, 8, 8><<<grid, 256>>>(agg1, W1, b1, h, N, 256, 128, 1);
    }

    // ---- Layer 2 ----
    k_norms_init<D2><<<nodeBlocks, 256>>>(h, hn, agg2, N);
    k_edge_pass<D2><<<edgeBlocks, 256>>>(h, hn, eix, agg2, E);
    {
        dim3 grid(1, (N + 127) / 128);
        k_sgemm<128, 64, 16, 8, 4><<<grid, 256>>>(agg2, W2, b2, out, N, 64, 256, 0);
    }

    k_logsoftmax64<<<(N * 32 + 255) / 256, 256>>>(out, N);
}